// round 1
// baseline (speedup 1.0000x reference)
#include <cuda_runtime.h>
#include <math.h>

// ---------------------------------------------------------------------------
// YOLOX loss, B=64, A=8400 (strides 8/16/32 on 640), M=50 targets, 80 classes.
// predictions: (64, 8400, 85) f32, targets: (64, 50, 5) f32, input_size: 640.
// out: [total, box_loss, obj_loss, cls_loss, num_fg] f32.
//
// Pass 1 (streaming): warp-per-anchor. Each warp:
//   - computes its anchor center analytically
//   - argmin over 50 GT centers (lane-parallel + shuffle reduce, first-idx tie)
//   - loads the 85-float prediction row coalesced (lane, lane+32, lane+64)
//   - obj BCE (all anchors), cls BCE vs one-hot + IoU loss (positives only)
//   - accumulates lane-locally; block reduce; 4 atomicAdds per block into
//     per-image accumulators in a __device__ global.
// Pass 2 (finalize): per-image normalization (num_pos-dependent) + batch sum.
// ---------------------------------------------------------------------------

#define NUM_A     8400
#define NUM_M     50
#define NUM_C     80
#define BLK       256
#define WARPS     (BLK / 32)
#define BLKS_IMG  42          // 42*8 = 336 warps/image -> 25 anchors/warp
#define FULLMASK  0xffffffffu

__device__ float g_acc[64 * 4];   // per image: obj_sum, cls_raw, box_raw, num_pos

__device__ __forceinline__ float bce(float x, float t) {
    // max(x,0) - x*t + log1p(exp(-|x|))  (stable BCE-with-logits)
    return fmaxf(x, 0.0f) - x * t + log1pf(__expf(-fabsf(x)));
}

__global__ void zero_acc_kernel() {
    int t = threadIdx.x;
    if (t < 256) g_acc[t] = 0.0f;
}

__global__ __launch_bounds__(BLK) void yolox_main_kernel(
    const float* __restrict__ pred,    // (64, 8400, 85)
    const float* __restrict__ tgt)     // (64, 50, 5)
{
    __shared__ float s_cx[NUM_M], s_cy[NUM_M];
    __shared__ float s_x1[NUM_M], s_y1[NUM_M], s_x2[NUM_M], s_y2[NUM_M];
    __shared__ float s_ta[NUM_M];
    __shared__ int   s_cls[NUM_M];
    __shared__ int   s_val[NUM_M];
    __shared__ float s_red[WARPS][4];

    const int img  = blockIdx.y;
    const int tid  = threadIdx.x;
    const int lane = tid & 31;
    const int warp = tid >> 5;

    if (tid < NUM_M) {
        const float* tr = tgt + ((size_t)img * NUM_M + tid) * 5;
        float c = tr[0];
        s_val[tid] = (c >= 0.0f) ? 1 : 0;
        s_cls[tid] = (int)c;
        float cx = tr[1] * 640.0f, cy = tr[2] * 640.0f;
        float w  = tr[3] * 640.0f, h  = tr[4] * 640.0f;
        s_cx[tid] = cx; s_cy[tid] = cy;
        float x1 = cx - w * 0.5f, y1 = cy - h * 0.5f;
        float x2 = cx + w * 0.5f, y2 = cy + h * 0.5f;
        s_x1[tid] = x1; s_y1[tid] = y1; s_x2[tid] = x2; s_y2[tid] = y2;
        s_ta[tid] = (x2 - x1) * (y2 - y1);
    }
    __syncthreads();

    const int   wglobal = blockIdx.x * WARPS + warp;
    const int   wstride = gridDim.x * WARPS;
    const float* base   = pred + (size_t)img * NUM_A * 85;

    float w_obj = 0.0f, w_cls = 0.0f, w_box = 0.0f, w_pos = 0.0f;

    for (int a = wglobal; a < NUM_A; a += wstride) {
        // anchor center
        float ax, ay;
        {
            int i, n, s;
            if (a < 6400)      { i = a;        n = 80; s = 8;  }
            else if (a < 8000) { i = a - 6400; n = 40; s = 16; }
            else               { i = a - 8000; n = 20; s = 32; }
            ax = (float)(i % n) * (float)s + (float)s * 0.5f;
            ay = (float)(i / n) * (float)s + (float)s * 0.5f;
        }

        // argmin over GT centers (first-index tie-break, matches jnp.argmin)
        float best = INFINITY; int bidx = 0;
        for (int m = lane; m < NUM_M; m += 32) {
            float dx = s_cx[m] - ax;
            float dy = s_cy[m] - ay;
            float d2 = s_val[m] ? (dx * dx + dy * dy) : INFINITY;
            if (d2 < best) { best = d2; bidx = m; }
        }
        for (int off = 16; off; off >>= 1) {
            float ob = __shfl_down_sync(FULLMASK, best, off);
            int   oi = __shfl_down_sync(FULLMASK, bidx, off);
            if (ob < best || (ob == best && oi < bidx)) { best = ob; bidx = oi; }
        }
        best = __shfl_sync(FULLMASK, best, 0);
        bidx = __shfl_sync(FULLMASK, bidx, 0);

        const bool  pos  = best < 4096.0f;   // DIST_THRESH_SQ
        const float posf = pos ? 1.0f : 0.0f;

        // coalesced row load: 85 floats via lane, lane+32, lane+64
        const float* row = base + (size_t)a * 85;
        float v0 = __ldg(row + lane);
        float v1 = __ldg(row + lane + 32);
        float v2 = (lane < 21) ? __ldg(row + lane + 64) : 0.0f;

        float px   = __shfl_sync(FULLMASK, v0, 0);
        float py   = __shfl_sync(FULLMASK, v0, 1);
        float pw   = __shfl_sync(FULLMASK, v0, 2);
        float ph   = __shfl_sync(FULLMASK, v0, 3);
        float pobj = __shfl_sync(FULLMASK, v0, 4);

        // classification BCE (positives only), lane-parallel over 80 classes
        const int mcls = s_cls[bidx];
        float csum = 0.0f;
        if (lane >= 5) csum += bce(v0, (lane - 5) == mcls ? 1.0f : 0.0f);
        csum += bce(v1, (lane + 27) == mcls ? 1.0f : 0.0f);
        if (lane < 21) csum += bce(v2, (lane + 59) == mcls ? 1.0f : 0.0f);
        w_cls += posf * csum;

        if (lane == 0) {
            w_obj += bce(pobj, posf);
            if (pos) {
                float ew = __expf(pw), eh = __expf(ph);
                float p1x = px - ew * 0.5f, p2x = px + ew * 0.5f;
                float p1y = py - eh * 0.5f, p2y = py + eh * 0.5f;
                float ix = fminf(p2x, s_x2[bidx]) - fmaxf(p1x, s_x1[bidx]);
                float iy = fminf(p2y, s_y2[bidx]) - fmaxf(p1y, s_y1[bidx]);
                float inter = fmaxf(ix, 0.0f) * fmaxf(iy, 0.0f);
                float pa    = (p2x - p1x) * (p2y - p1y);
                float uni   = pa + s_ta[bidx] - inter;
                w_box += 1.0f - inter / (uni + 1e-6f);
                w_pos += 1.0f;
            }
        }
    }

    // warp reduce cls sum (others already live on lane 0)
    for (int off = 16; off; off >>= 1)
        w_cls += __shfl_down_sync(FULLMASK, w_cls, off);

    if (lane == 0) {
        s_red[warp][0] = w_obj;
        s_red[warp][1] = w_cls;
        s_red[warp][2] = w_box;
        s_red[warp][3] = w_pos;
    }
    __syncthreads();

    if (tid == 0) {
        float o = 0.0f, c = 0.0f, b = 0.0f, p = 0.0f;
        #pragma unroll
        for (int i = 0; i < WARPS; i++) {
            o += s_red[i][0]; c += s_red[i][1];
            b += s_red[i][2]; p += s_red[i][3];
        }
        atomicAdd(&g_acc[img * 4 + 0], o);
        atomicAdd(&g_acc[img * 4 + 1], c);
        atomicAdd(&g_acc[img * 4 + 2], b);
        atomicAdd(&g_acc[img * 4 + 3], p);
    }
}

__global__ void finalize_kernel(float* __restrict__ out) {
    __shared__ float s0[2][4];
    int i = threadIdx.x;   // 64 threads, one per image

    float np  = g_acc[i * 4 + 3];
    float obj = g_acc[i * 4 + 0] / 8400.0f;
    float den = fmaxf(np, 1.0f);
    float cls = (np > 0.0f) ? g_acc[i * 4 + 1] / (den * 80.0f) : 0.0f;
    float box = (np > 0.0f) ? g_acc[i * 4 + 2] / den            : 0.0f;

    for (int off = 16; off; off >>= 1) {
        obj += __shfl_down_sync(FULLMASK, obj, off);
        cls += __shfl_down_sync(FULLMASK, cls, off);
        box += __shfl_down_sync(FULLMASK, box, off);
        np  += __shfl_down_sync(FULLMASK, np,  off);
    }
    if ((i & 31) == 0) {
        s0[i >> 5][0] = obj; s0[i >> 5][1] = cls;
        s0[i >> 5][2] = box; s0[i >> 5][3] = np;
    }
    __syncthreads();
    if (i == 0) {
        float o = s0[0][0] + s0[1][0];
        float c = s0[0][1] + s0[1][1];
        float b = s0[0][2] + s0[1][2];
        float p = s0[0][3] + s0[1][3];
        out[0] = 5.0f * b + o + c;
        out[1] = b;
        out[2] = o;
        out[3] = c;
        out[4] = p;
    }
}

extern "C" void kernel_launch(void* const* d_in, const int* in_sizes, int n_in,
                              void* d_out, int out_size) {
    const float* pred = (const float*)d_in[0];
    const float* tgt  = (const float*)d_in[1];
    // d_in[2] = input_size (always 640; anchors computed analytically)
    float* out = (float*)d_out;

    zero_acc_kernel<<<1, 256>>>();
    dim3 grid(BLKS_IMG, 64);
    yolox_main_kernel<<<grid, BLK>>>(pred, tgt);
    finalize_kernel<<<1, 64>>>(out);
}

// round 3
// speedup vs baseline: 1.5968x; 1.5968x over previous
#include <cuda_runtime.h>
#include <math.h>

// ---------------------------------------------------------------------------
// YOLOX loss, B=64, A=8400, M=50 targets, 80 classes. One streaming pass,
// warp-per-anchor, fast softplus-based BCE, skip class loads for negatives,
// deterministic block partials (no atomics, no zero kernel) + tiny finalize.
// R3: removed the dead lane-0-only __shfl_sync(0x1f,...) block that deadlocked
// the warp (non-uniform collective). All shuffles now provably warp-converged.
// ---------------------------------------------------------------------------

#define NUM_A     8400
#define NUM_M     50
#define BLK       256
#define WARPS     (BLK / 32)
#define BLKS_IMG  42          // 42*8 = 336 warps/image -> 25 anchors/warp
#define FULLMASK  0xffffffffu

// per (img, block): obj_sum, cls_raw, box_raw, num_pos
__device__ float g_part[64 * BLKS_IMG * 4];

__device__ __forceinline__ float softplus(float x) {
    // log(1 + e^x) = max(x,0) + log(1 + e^{-|x|}); arg of log in (1,2] -> __logf ok
    return fmaxf(x, 0.0f) + __logf(1.0f + __expf(-fabsf(x)));
}

__global__ __launch_bounds__(BLK) void yolox_main_kernel(
    const float* __restrict__ pred,    // (64, 8400, 85)
    const float* __restrict__ tgt)     // (64, 50, 5)
{
    __shared__ float2 s_ctr[NUM_M];                      // gt centers (or 1e9 if invalid)
    __shared__ float  s_x1[NUM_M], s_y1[NUM_M], s_x2[NUM_M], s_y2[NUM_M];
    __shared__ float  s_ta[NUM_M];
    __shared__ int    s_cls[NUM_M];
    __shared__ float  s_red[WARPS][4];

    const int img  = blockIdx.y;
    const int tid  = threadIdx.x;
    const int lane = tid & 31;
    const int warp = tid >> 5;

    if (tid < NUM_M) {
        const float* tr = tgt + ((size_t)img * NUM_M + tid) * 5;
        float c = tr[0];
        bool valid = (c >= 0.0f);
        s_cls[tid] = (int)c;
        float cx = tr[1] * 640.0f, cy = tr[2] * 640.0f;
        float w  = tr[3] * 640.0f, h  = tr[4] * 640.0f;
        s_ctr[tid] = valid ? make_float2(cx, cy) : make_float2(1e9f, 1e9f);
        float x1 = cx - w * 0.5f, y1 = cy - h * 0.5f;
        float x2 = cx + w * 0.5f, y2 = cy + h * 0.5f;
        s_x1[tid] = x1; s_y1[tid] = y1; s_x2[tid] = x2; s_y2[tid] = y2;
        s_ta[tid] = (x2 - x1) * (y2 - y1);
    }
    __syncthreads();

    const int    wglobal = blockIdx.x * WARPS + warp;
    const int    wstride = BLKS_IMG * WARPS;
    const float* base    = pred + (size_t)img * NUM_A * 85;

    float w_obj = 0.0f, w_cls = 0.0f, w_box = 0.0f, w_pos = 0.0f;

    for (int a = wglobal; a < NUM_A; a += wstride) {
        // anchor center (analytic)
        float ax, ay;
        {
            int i, n, s;
            if (a < 6400)      { i = a;        n = 80; s = 8;  }
            else if (a < 8000) { i = a - 6400; n = 40; s = 16; }
            else               { i = a - 8000; n = 20; s = 32; }
            ax = (float)(i % n) * (float)s + (float)s * 0.5f;
            ay = (float)(i / n) * (float)s + (float)s * 0.5f;
        }

        // argmin over 50 GT centers (lane-parallel + shuffle reduce, first-idx tie)
        float best = INFINITY; int bidx = 0;
        #pragma unroll
        for (int k = 0; k < 2; k++) {
            int m = lane + k * 32;
            if (m < NUM_M) {
                float2 c = s_ctr[m];
                float dx = c.x - ax, dy = c.y - ay;
                float d2 = fmaf(dx, dx, dy * dy);
                if (d2 < best) { best = d2; bidx = m; }
            }
        }
        #pragma unroll
        for (int off = 16; off; off >>= 1) {
            float ob = __shfl_down_sync(FULLMASK, best, off);
            int   oi = __shfl_down_sync(FULLMASK, bidx, off);
            if (ob < best || (ob == best && oi < bidx)) { best = ob; bidx = oi; }
        }
        best = __shfl_sync(FULLMASK, best, 0);
        bidx = __shfl_sync(FULLMASK, bidx, 0);

        const bool pos = best < 4096.0f;     // DIST_THRESH_SQ (warp-uniform)
        const float* row = base + (size_t)a * 85;

        if (pos) {
            float v0 = __ldg(row + lane);
            float v1 = __ldg(row + lane + 32);
            float v2 = (lane < 21) ? __ldg(row + lane + 64) : 0.0f;

            // cls BCE: sum softplus(all class logits) - matched logit
            const int mcls = s_cls[bidx];
            float sp = 0.0f, msub = 0.0f;
            if (lane >= 5) {
                sp += softplus(v0);
                if (lane - 5 == mcls) msub = v0;
            }
            sp += softplus(v1);
            if (lane + 27 == mcls) msub = v1;
            if (lane < 21) {
                sp += softplus(v2);
                if (lane + 59 == mcls) msub = v2;
            }
            w_cls += sp - msub;

            // broadcast box params + obj logit (warp-collective, all lanes)
            float px   = __shfl_sync(FULLMASK, v0, 0);
            float py   = __shfl_sync(FULLMASK, v0, 1);
            float pw   = __shfl_sync(FULLMASK, v0, 2);
            float ph   = __shfl_sync(FULLMASK, v0, 3);
            float pobj = __shfl_sync(FULLMASK, v0, 4);
            if (lane == 0) {
                float ew = __expf(pw), eh = __expf(ph);
                float p1x = px - ew * 0.5f, p2x = px + ew * 0.5f;
                float p1y = py - eh * 0.5f, p2y = py + eh * 0.5f;
                float ix = fminf(p2x, s_x2[bidx]) - fmaxf(p1x, s_x1[bidx]);
                float iy = fminf(p2y, s_y2[bidx]) - fmaxf(p1y, s_y1[bidx]);
                float inter = fmaxf(ix, 0.0f) * fmaxf(iy, 0.0f);
                float pa    = (p2x - p1x) * (p2y - p1y);
                float uni   = pa + s_ta[bidx] - inter;
                w_box += 1.0f - inter / (uni + 1e-6f);
                w_pos += 1.0f;
                w_obj += softplus(pobj) - pobj;   // bce(pobj, 1)
            }
        } else {
            if (lane == 0) {
                float pobj = __ldg(row + 4);
                w_obj += softplus(pobj);          // bce(pobj, 0)
            }
        }
    }

    // warp reduce cls sum (others already live on lane 0)
    #pragma unroll
    for (int off = 16; off; off >>= 1)
        w_cls += __shfl_down_sync(FULLMASK, w_cls, off);

    if (lane == 0) {
        s_red[warp][0] = w_obj;
        s_red[warp][1] = w_cls;
        s_red[warp][2] = w_box;
        s_red[warp][3] = w_pos;
    }
    __syncthreads();

    if (tid == 0) {
        float o = 0.0f, c = 0.0f, b = 0.0f, p = 0.0f;
        #pragma unroll
        for (int i = 0; i < WARPS; i++) {
            o += s_red[i][0]; c += s_red[i][1];
            b += s_red[i][2]; p += s_red[i][3];
        }
        float* dst = g_part + ((size_t)img * BLKS_IMG + blockIdx.x) * 4;
        dst[0] = o; dst[1] = c; dst[2] = b; dst[3] = p;
    }
}

__global__ void finalize_kernel(float* __restrict__ out) {
    // 256 threads: img = tid>>2, comp = tid&3 (0=obj,1=cls,2=box,3=np)
    __shared__ float sw[8][4];
    __shared__ float sfin[4];
    const int tid  = threadIdx.x;
    const int lane = tid & 31;
    const int warp = tid >> 5;
    const int img  = tid >> 2;
    const int comp = tid & 3;

    float s = 0.0f;
    const float* p = g_part + (size_t)img * BLKS_IMG * 4 + comp;
    #pragma unroll
    for (int b = 0; b < BLKS_IMG; b++) s += p[b * 4];

    // np lives on the comp==3 thread of this quad (same warp)
    float np = __shfl_sync(FULLMASK, s, lane | 3);
    float den = fmaxf(np, 1.0f);

    float v;
    if (comp == 0)      v = s / 8400.0f;
    else if (comp == 1) v = (np > 0.0f) ? s / (den * 80.0f) : 0.0f;
    else if (comp == 2) v = (np > 0.0f) ? s / den : 0.0f;
    else                v = s;

    // reduce across images: same comp at lane stride 4
    #pragma unroll
    for (int off = 4; off < 32; off <<= 1)
        v += __shfl_down_sync(FULLMASK, v, off);

    if (lane < 4) sw[warp][lane] = v;   // lane==comp here
    __syncthreads();

    if (tid < 4) {
        float t = 0.0f;
        #pragma unroll
        for (int w = 0; w < 8; w++) t += sw[w][tid];
        sfin[tid] = t;
    }
    __syncthreads();

    if (tid == 0) {
        float obj = sfin[0], cls = sfin[1], box = sfin[2], np = sfin[3];
        out[0] = 5.0f * box + obj + cls;
        out[1] = box;
        out[2] = obj;
        out[3] = cls;
        out[4] = np;
    }
}

extern "C" void kernel_launch(void* const* d_in, const int* in_sizes, int n_in,
                              void* d_out, int out_size) {
    const float* pred = (const float*)d_in[0];
    const float* tgt  = (const float*)d_in[1];
    float* out = (float*)d_out;

    dim3 grid(BLKS_IMG, 64);
    yolox_main_kernel<<<grid, BLK>>>(pred, tgt);
    finalize_kernel<<<1, 256>>>(out);
}

// round 4
// speedup vs baseline: 3.5936x; 2.2505x over previous
#include <cuda_runtime.h>
#include <math.h>

// ---------------------------------------------------------------------------
// YOLOX loss, B=64, A=8400, M=50, 80 classes.
// R4: thread-per-anchor argmin (no shuffle chains), ballot-driven warp-
// cooperative class-BCE over positive rows, per-thread IoU from L1 hits.
// ---------------------------------------------------------------------------

#define NUM_A     8400
#define NUM_M     50
#define BLK       256
#define WARPS     (BLK / 32)
#define BLKS_IMG  33          // 33*256 = 8448 threads >= 8400 anchors, 1 anchor/thread
#define FULLMASK  0xffffffffu

// per (img, block): obj_sum, cls_raw, box_raw, num_pos
__device__ float g_part[64 * BLKS_IMG * 4];

__device__ __forceinline__ float softplus(float x) {
    // log(1+e^x) = max(x,0) + log(1 + e^{-|x|})
    return fmaxf(x, 0.0f) + __logf(1.0f + __expf(-fabsf(x)));
}

__global__ __launch_bounds__(BLK) void yolox_main_kernel(
    const float* __restrict__ pred,    // (64, 8400, 85)
    const float* __restrict__ tgt)     // (64, 50, 5)
{
    __shared__ float2 s_ctr[NUM_M];    // gt centers (1e9 if invalid)
    __shared__ float  s_x1[NUM_M], s_y1[NUM_M], s_x2[NUM_M], s_y2[NUM_M];
    __shared__ float  s_ta[NUM_M];
    __shared__ int    s_cls[NUM_M];
    __shared__ float  s_red[WARPS][4];

    const int img  = blockIdx.y;
    const int tid  = threadIdx.x;
    const int lane = tid & 31;
    const int warp = tid >> 5;

    if (tid < NUM_M) {
        const float* tr = tgt + ((size_t)img * NUM_M + tid) * 5;
        float c = tr[0];
        bool ok = (c >= 0.0f);
        s_cls[tid] = (int)c;
        float cx = tr[1] * 640.0f, cy = tr[2] * 640.0f;
        float w  = tr[3] * 640.0f, h  = tr[4] * 640.0f;
        s_ctr[tid] = ok ? make_float2(cx, cy) : make_float2(1e9f, 1e9f);
        float x1 = cx - w * 0.5f, y1 = cy - h * 0.5f;
        float x2 = cx + w * 0.5f, y2 = cy + h * 0.5f;
        s_x1[tid] = x1; s_y1[tid] = y1; s_x2[tid] = x2; s_y2[tid] = y2;
        s_ta[tid] = (x2 - x1) * (y2 - y1);
    }
    __syncthreads();

    const int    a     = blockIdx.x * BLK + tid;   // this thread's anchor
    const bool   valid = (a < NUM_A);
    const float* base  = pred + (size_t)img * NUM_A * 85;

    // ---- phase 1: per-thread anchor center + argmin over 50 GTs ----
    float ax = 0.0f, ay = 0.0f;
    if (valid) {
        int i, n, s;
        if (a < 6400)      { i = a;        n = 80; s = 8;  }
        else if (a < 8000) { i = a - 6400; n = 40; s = 16; }
        else               { i = a - 8000; n = 20; s = 32; }
        ax = (float)(i % n) * (float)s + (float)s * 0.5f;
        ay = (float)(i / n) * (float)s + (float)s * 0.5f;
    }

    float b0 = INFINITY, b1 = INFINITY;
    int   i0 = 0,        i1 = 1;
    #pragma unroll 5
    for (int m = 0; m < NUM_M; m += 2) {
        float2 c0 = s_ctr[m];
        float2 c1 = s_ctr[m + 1];
        float dx0 = c0.x - ax, dy0 = c0.y - ay;
        float dx1 = c1.x - ax, dy1 = c1.y - ay;
        float d20 = fmaf(dx0, dx0, dy0 * dy0);
        float d21 = fmaf(dx1, dx1, dy1 * dy1);
        if (d20 < b0) { b0 = d20; i0 = m; }
        if (d21 < b1) { b1 = d21; i1 = m + 1; }
    }
    float best = b0; int bidx = i0;
    if (b1 < b0 || (b1 == b0 && i1 < i0)) { best = b1; bidx = i1; }

    const bool  pos  = valid && (best < 4096.0f);   // DIST_THRESH_SQ
    const float posf = pos ? 1.0f : 0.0f;

    // obj BCE per-thread: softplus(x) - posf*x
    float w_obj = 0.0f;
    if (valid) {
        float pobj = __ldg(base + (size_t)a * 85 + 4);
        w_obj = softplus(pobj) - posf * pobj;
    }

    // ---- phase 2: warp-cooperative cls BCE over positive rows ----
    const int mcls_own = s_cls[bidx];
    const int wbase    = blockIdx.x * BLK + warp * 32;
    float w_cls = 0.0f;

    unsigned pmask = __ballot_sync(FULLMASK, pos);
    while (pmask) {
        int p = __ffs(pmask) - 1;
        pmask &= pmask - 1;
        int mcls = __shfl_sync(FULLMASK, mcls_own, p);
        const float* row = base + (size_t)(wbase + p) * 85;
        float v0 = __ldg(row + lane);
        float v1 = __ldg(row + lane + 32);
        float v2 = (lane < 21) ? __ldg(row + lane + 64) : 0.0f;

        float sp = 0.0f, msub = 0.0f;
        if (lane >= 5) {
            sp += softplus(v0);
            if (lane - 5 == mcls) msub = v0;
        }
        sp += softplus(v1);
        if (lane + 27 == mcls) msub = v1;
        if (lane < 21) {
            sp += softplus(v2);
            if (lane + 59 == mcls) msub = v2;
        }
        w_cls += sp - msub;
    }

    // ---- phase 3: per-thread IoU for own positive anchor (L1 hits) ----
    float w_box = 0.0f, w_pos = 0.0f;
    if (pos) {
        const float* row = base + (size_t)a * 85;
        float px = __ldg(row + 0);
        float py = __ldg(row + 1);
        float pw = __ldg(row + 2);
        float ph = __ldg(row + 3);
        float ew = __expf(pw), eh = __expf(ph);
        float p1x = px - ew * 0.5f, p2x = px + ew * 0.5f;
        float p1y = py - eh * 0.5f, p2y = py + eh * 0.5f;
        float ix = fminf(p2x, s_x2[bidx]) - fmaxf(p1x, s_x1[bidx]);
        float iy = fminf(p2y, s_y2[bidx]) - fmaxf(p1y, s_y1[bidx]);
        float inter = fmaxf(ix, 0.0f) * fmaxf(iy, 0.0f);
        float pa    = (p2x - p1x) * (p2y - p1y);
        float uni   = pa + s_ta[bidx] - inter;
        w_box = 1.0f - inter / (uni + 1e-6f);
        w_pos = 1.0f;
    }

    // ---- reduction: warp -> block -> g_part ----
    #pragma unroll
    for (int off = 16; off; off >>= 1) {
        w_obj += __shfl_down_sync(FULLMASK, w_obj, off);
        w_cls += __shfl_down_sync(FULLMASK, w_cls, off);
        w_box += __shfl_down_sync(FULLMASK, w_box, off);
        w_pos += __shfl_down_sync(FULLMASK, w_pos, off);
    }
    if (lane == 0) {
        s_red[warp][0] = w_obj;
        s_red[warp][1] = w_cls;
        s_red[warp][2] = w_box;
        s_red[warp][3] = w_pos;
    }
    __syncthreads();

    if (tid == 0) {
        float o = 0.0f, c = 0.0f, b = 0.0f, p = 0.0f;
        #pragma unroll
        for (int i = 0; i < WARPS; i++) {
            o += s_red[i][0]; c += s_red[i][1];
            b += s_red[i][2]; p += s_red[i][3];
        }
        float* dst = g_part + ((size_t)img * BLKS_IMG + blockIdx.x) * 4;
        dst[0] = o; dst[1] = c; dst[2] = b; dst[3] = p;
    }
}

__global__ void finalize_kernel(float* __restrict__ out) {
    // 256 threads: img = tid>>2, comp = tid&3 (0=obj,1=cls,2=box,3=np)
    __shared__ float sw[8][4];
    __shared__ float sfin[4];
    const int tid  = threadIdx.x;
    const int lane = tid & 31;
    const int warp = tid >> 5;
    const int img  = tid >> 2;
    const int comp = tid & 3;

    float s = 0.0f;
    const float* p = g_part + (size_t)img * BLKS_IMG * 4 + comp;
    #pragma unroll
    for (int b = 0; b < BLKS_IMG; b++) s += p[b * 4];

    float np  = __shfl_sync(FULLMASK, s, lane | 3);
    float den = fmaxf(np, 1.0f);

    float v;
    if (comp == 0)      v = s / 8400.0f;
    else if (comp == 1) v = (np > 0.0f) ? s / (den * 80.0f) : 0.0f;
    else if (comp == 2) v = (np > 0.0f) ? s / den : 0.0f;
    else                v = s;

    #pragma unroll
    for (int off = 4; off < 32; off <<= 1)
        v += __shfl_down_sync(FULLMASK, v, off);

    if (lane < 4) sw[warp][lane] = v;
    __syncthreads();

    if (tid < 4) {
        float t = 0.0f;
        #pragma unroll
        for (int w = 0; w < 8; w++) t += sw[w][tid];
        sfin[tid] = t;
    }
    __syncthreads();

    if (tid == 0) {
        float obj = sfin[0], cls = sfin[1], box = sfin[2], np = sfin[3];
        out[0] = 5.0f * box + obj + cls;
        out[1] = box;
        out[2] = obj;
        out[3] = cls;
        out[4] = np;
    }
}

extern "C" void kernel_launch(void* const* d_in, const int* in_sizes, int n_in,
                              void* d_out, int out_size) {
    const float* pred = (const float*)d_in[0];
    const float* tgt  = (const float*)d_in[1];
    float* out = (float*)d_out;

    dim3 grid(BLKS_IMG, 64);
    yolox_main_kernel<<<grid, BLK>>>(pred, tgt);
    finalize_kernel<<<1, 256>>>(out);
}

// round 5
// speedup vs baseline: 3.6724x; 1.0219x over previous
#include <cuda_runtime.h>
#include <math.h>

// ---------------------------------------------------------------------------
// YOLOX loss, B=64, A=8400, M=50, 80 classes.
// R5: R4 (thread-per-anchor argmin + ballot-cooperative cls BCE) plus:
//   - depth-1 software pipeline of the positive-row loads in phase 2
//   - finalize fused via fence+ticket last-block reduction (single launch)
// ---------------------------------------------------------------------------

#define NUM_A     8400
#define NUM_M     50
#define BLK       256
#define WARPS     (BLK / 32)
#define BLKS_IMG  33          // 33*256 = 8448 threads >= 8400 anchors
#define NBLOCKS   (BLKS_IMG * 64)
#define FULLMASK  0xffffffffu

// per (img, block): obj_sum, cls_raw, box_raw, num_pos
__device__ float    g_part[64 * BLKS_IMG * 4];
__device__ unsigned g_ticket = 0;

__device__ __forceinline__ float softplus(float x) {
    // log(1+e^x) = max(x,0) + log(1 + e^{-|x|});  arg of log in (1,2]
    return fmaxf(x, 0.0f) + __logf(1.0f + __expf(-fabsf(x)));
}

__global__ __launch_bounds__(BLK) void yolox_main_kernel(
    const float* __restrict__ pred,    // (64, 8400, 85)
    const float* __restrict__ tgt,     // (64, 50, 5)
    float* __restrict__ out)           // [5]
{
    __shared__ float2 s_ctr[NUM_M];    // gt centers (1e9 if invalid)
    __shared__ float  s_x1[NUM_M], s_y1[NUM_M], s_x2[NUM_M], s_y2[NUM_M];
    __shared__ float  s_ta[NUM_M];
    __shared__ int    s_cls[NUM_M];
    __shared__ float  s_red[WARPS][4];
    __shared__ int    s_last;

    const int img  = blockIdx.y;
    const int tid  = threadIdx.x;
    const int lane = tid & 31;
    const int warp = tid >> 5;

    if (tid < NUM_M) {
        const float* tr = tgt + ((size_t)img * NUM_M + tid) * 5;
        float c = tr[0];
        bool ok = (c >= 0.0f);
        s_cls[tid] = (int)c;
        float cx = tr[1] * 640.0f, cy = tr[2] * 640.0f;
        float w  = tr[3] * 640.0f, h  = tr[4] * 640.0f;
        s_ctr[tid] = ok ? make_float2(cx, cy) : make_float2(1e9f, 1e9f);
        float x1 = cx - w * 0.5f, y1 = cy - h * 0.5f;
        float x2 = cx + w * 0.5f, y2 = cy + h * 0.5f;
        s_x1[tid] = x1; s_y1[tid] = y1; s_x2[tid] = x2; s_y2[tid] = y2;
        s_ta[tid] = (x2 - x1) * (y2 - y1);
    }
    __syncthreads();

    const int    a     = blockIdx.x * BLK + tid;
    const bool   valid = (a < NUM_A);
    const float* base  = pred + (size_t)img * NUM_A * 85;

    // ---- phase 1: per-thread anchor center + argmin over 50 GTs ----
    float ax = 0.0f, ay = 0.0f;
    if (valid) {
        int i, n, s;
        if (a < 6400)      { i = a;        n = 80; s = 8;  }
        else if (a < 8000) { i = a - 6400; n = 40; s = 16; }
        else               { i = a - 8000; n = 20; s = 32; }
        ax = (float)(i % n) * (float)s + (float)s * 0.5f;
        ay = (float)(i / n) * (float)s + (float)s * 0.5f;
    }

    float b0 = INFINITY, b1 = INFINITY;
    int   i0 = 0,        i1 = 1;
    #pragma unroll 5
    for (int m = 0; m < NUM_M; m += 2) {
        float2 c0 = s_ctr[m];
        float2 c1 = s_ctr[m + 1];
        float dx0 = c0.x - ax, dy0 = c0.y - ay;
        float dx1 = c1.x - ax, dy1 = c1.y - ay;
        float d20 = fmaf(dx0, dx0, dy0 * dy0);
        float d21 = fmaf(dx1, dx1, dy1 * dy1);
        if (d20 < b0) { b0 = d20; i0 = m; }
        if (d21 < b1) { b1 = d21; i1 = m + 1; }
    }
    float best = b0; int bidx = i0;
    if (b1 < b0 || (b1 == b0 && i1 < i0)) { best = b1; bidx = i1; }

    const bool  pos  = valid && (best < 4096.0f);   // DIST_THRESH_SQ
    const float posf = pos ? 1.0f : 0.0f;

    // obj BCE per-thread: softplus(x) - posf*x
    float w_obj = 0.0f;
    if (valid) {
        float pobj = __ldg(base + (size_t)a * 85 + 4);
        w_obj = softplus(pobj) - posf * pobj;
    }

    // ---- phase 2: warp-cooperative cls BCE, depth-1 pipelined loads ----
    const int mcls_own = s_cls[bidx];
    const int wbase    = blockIdx.x * BLK + warp * 32;
    float w_cls = 0.0f;

    unsigned pmask = __ballot_sync(FULLMASK, pos);   // identical in all lanes
    int   pcur = -1;
    float v0 = 0.0f, v1 = 0.0f, v2 = 0.0f;
    if (pmask) {
        pcur = __ffs(pmask) - 1;
        pmask &= pmask - 1;
        const float* row = base + (size_t)(wbase + pcur) * 85;
        v0 = __ldg(row + lane);
        v1 = __ldg(row + lane + 32);
        v2 = (lane < 21) ? __ldg(row + lane + 64) : 0.0f;
    }
    while (pcur >= 0) {
        // prefetch next positive row
        int   pnext = -1;
        float n0 = 0.0f, n1 = 0.0f, n2 = 0.0f;
        if (pmask) {
            pnext = __ffs(pmask) - 1;
            pmask &= pmask - 1;
            const float* row = base + (size_t)(wbase + pnext) * 85;
            n0 = __ldg(row + lane);
            n1 = __ldg(row + lane + 32);
            n2 = (lane < 21) ? __ldg(row + lane + 64) : 0.0f;
        }

        // process current row
        int mcls = __shfl_sync(FULLMASK, mcls_own, pcur);
        float sp = 0.0f, msub = 0.0f;
        if (lane >= 5) {
            sp += softplus(v0);
            if (lane - 5 == mcls) msub = v0;
        }
        sp += softplus(v1);
        if (lane + 27 == mcls) msub = v1;
        if (lane < 21) {
            sp += softplus(v2);
            if (lane + 59 == mcls) msub = v2;
        }
        w_cls += sp - msub;

        pcur = pnext; v0 = n0; v1 = n1; v2 = n2;
    }

    // ---- phase 3: per-thread IoU for own positive anchor (L1 hits) ----
    float w_box = 0.0f, w_pos = 0.0f;
    if (pos) {
        const float* row = base + (size_t)a * 85;
        float px = __ldg(row + 0);
        float py = __ldg(row + 1);
        float pw = __ldg(row + 2);
        float ph = __ldg(row + 3);
        float ew = __expf(pw), eh = __expf(ph);
        float p1x = px - ew * 0.5f, p2x = px + ew * 0.5f;
        float p1y = py - eh * 0.5f, p2y = py + eh * 0.5f;
        float ix = fminf(p2x, s_x2[bidx]) - fmaxf(p1x, s_x1[bidx]);
        float iy = fminf(p2y, s_y2[bidx]) - fmaxf(p1y, s_y1[bidx]);
        float inter = fmaxf(ix, 0.0f) * fmaxf(iy, 0.0f);
        float pa    = (p2x - p1x) * (p2y - p1y);
        float uni   = pa + s_ta[bidx] - inter;
        w_box = 1.0f - inter / (uni + 1e-6f);
        w_pos = 1.0f;
    }

    // ---- reduction: warp -> block -> g_part ----
    #pragma unroll
    for (int off = 16; off; off >>= 1) {
        w_obj += __shfl_down_sync(FULLMASK, w_obj, off);
        w_cls += __shfl_down_sync(FULLMASK, w_cls, off);
        w_box += __shfl_down_sync(FULLMASK, w_box, off);
        w_pos += __shfl_down_sync(FULLMASK, w_pos, off);
    }
    if (lane == 0) {
        s_red[warp][0] = w_obj;
        s_red[warp][1] = w_cls;
        s_red[warp][2] = w_box;
        s_red[warp][3] = w_pos;
    }
    __syncthreads();

    if (tid == 0) {
        float o = 0.0f, c = 0.0f, b = 0.0f, p = 0.0f;
        #pragma unroll
        for (int i = 0; i < WARPS; i++) {
            o += s_red[i][0]; c += s_red[i][1];
            b += s_red[i][2]; p += s_red[i][3];
        }
        float* dst = g_part + ((size_t)img * BLKS_IMG + blockIdx.x) * 4;
        dst[0] = o; dst[1] = c; dst[2] = b; dst[3] = p;
        __threadfence();
        unsigned t = atomicAdd(&g_ticket, 1u);
        s_last = (t == NBLOCKS - 1) ? 1 : 0;
    }
    __syncthreads();

    // ---- last block: final reduction (deterministic values) ----
    if (s_last) {
        __shared__ float sw[8][4];
        __shared__ float sfin[4];
        const int rimg  = tid >> 2;        // 0..63
        const int comp  = tid & 3;         // 0=obj,1=cls,2=box,3=np

        float s = 0.0f;
        const float* p = g_part + (size_t)rimg * BLKS_IMG * 4 + comp;
        #pragma unroll
        for (int b = 0; b < BLKS_IMG; b++) s += p[b * 4];

        float np  = __shfl_sync(FULLMASK, s, lane | 3);
        float den = fmaxf(np, 1.0f);

        float v;
        if (comp == 0)      v = s / 8400.0f;
        else if (comp == 1) v = (np > 0.0f) ? s / (den * 80.0f) : 0.0f;
        else if (comp == 2) v = (np > 0.0f) ? s / den : 0.0f;
        else                v = s;

        #pragma unroll
        for (int off = 4; off < 32; off <<= 1)
            v += __shfl_down_sync(FULLMASK, v, off);

        if (lane < 4) sw[warp][lane] = v;
        __syncthreads();

        if (tid < 4) {
            float t = 0.0f;
            #pragma unroll
            for (int w = 0; w < 8; w++) t += sw[w][tid];
            sfin[tid] = t;
        }
        __syncthreads();

        if (tid == 0) {
            float obj = sfin[0], cls = sfin[1], box = sfin[2], np = sfin[3];
            out[0] = 5.0f * box + obj + cls;
            out[1] = box;
            out[2] = obj;
            out[3] = cls;
            out[4] = np;
            g_ticket = 0;      // reset for next (graph-replayed) launch
        }
    }
}

extern "C" void kernel_launch(void* const* d_in, const int* in_sizes, int n_in,
                              void* d_out, int out_size) {
    const float* pred = (const float*)d_in[0];
    const float* tgt  = (const float*)d_in[1];
    float* out = (float*)d_out;

    dim3 grid(BLKS_IMG, 64);
    yolox_main_kernel<<<grid, BLK>>>(pred, tgt, out);
}

// round 6
// speedup vs baseline: 4.8251x; 1.3139x over previous
#include <cuda_runtime.h>
#include <math.h>

// ---------------------------------------------------------------------------
// YOLOX loss, B=64, A=8400, M=50, 80 classes.
// R6: phase-2 loop stripped to pure softplus arithmetic:
//   - matched-class logit handled OUTSIDE the loop via one scalar load
//     (sum_c bce(x_c, onehot) == sum_c softplus(x_c) - x_matched)
//   - clean 32/32/16 lane mapping, -60 sentinel for the 16-wide tail
//   - branch-free 2-rows-per-iteration (warp-uniform selects, no BSSY storms)
//   - row[0..4] loaded before argmin (latency hidden); phase 3 is reg-only
//   - exp2/log2 softplus; fused ticket finalize (single launch)
// ---------------------------------------------------------------------------

#define NUM_A     8400
#define NUM_M     50
#define BLK       256
#define WARPS     (BLK / 32)
#define BLKS_IMG  33          // 33*256 = 8448 threads >= 8400 anchors
#define NBLOCKS   (BLKS_IMG * 64)
#define FULLMASK  0xffffffffu

// per (img, block): obj_sum, cls_raw, box_raw, num_pos
__device__ float    g_part[64 * BLKS_IMG * 4];
__device__ unsigned g_ticket = 0;

__device__ __forceinline__ float sp(float x) {
    // softplus: max(x,0) + ln2 * log2(1 + 2^(-|x|*log2e));  sp(-60) == 0.0f exactly
    float t = exp2f(-1.4426950408889634f * fabsf(x));
    return fmaf(__log2f(1.0f + t), 0.6931471805599453f, fmaxf(x, 0.0f));
}

__global__ __launch_bounds__(BLK) void yolox_main_kernel(
    const float* __restrict__ pred,    // (64, 8400, 85)
    const float* __restrict__ tgt,     // (64, 50, 5)
    float* __restrict__ out)           // [5]
{
    __shared__ float2 s_ctr[NUM_M];    // gt centers (1e9 if invalid)
    __shared__ float  s_x1[NUM_M], s_y1[NUM_M], s_x2[NUM_M], s_y2[NUM_M];
    __shared__ float  s_ta[NUM_M];
    __shared__ int    s_cls[NUM_M];
    __shared__ float  s_red[WARPS][4];
    __shared__ int    s_last;

    const int img  = blockIdx.y;
    const int tid  = threadIdx.x;
    const int lane = tid & 31;
    const int warp = tid >> 5;

    if (tid < NUM_M) {
        const float* tr = tgt + ((size_t)img * NUM_M + tid) * 5;
        float c = tr[0];
        bool ok = (c >= 0.0f);
        s_cls[tid] = (int)c;
        float cx = tr[1] * 640.0f, cy = tr[2] * 640.0f;
        float w  = tr[3] * 640.0f, h  = tr[4] * 640.0f;
        s_ctr[tid] = ok ? make_float2(cx, cy) : make_float2(1e9f, 1e9f);
        float x1 = cx - w * 0.5f, y1 = cy - h * 0.5f;
        float x2 = cx + w * 0.5f, y2 = cy + h * 0.5f;
        s_x1[tid] = x1; s_y1[tid] = y1; s_x2[tid] = x2; s_y2[tid] = y2;
        s_ta[tid] = (x2 - x1) * (y2 - y1);
    }
    __syncthreads();

    const int    a     = blockIdx.x * BLK + tid;
    const bool   valid = (a < NUM_A);
    const float* base  = pred + (size_t)img * NUM_A * 85;
    const float* myrow = base + (size_t)a * 85;

    // ---- early loads: row[0..4] (hidden under argmin) ----
    float r0 = 0.0f, r1 = 0.0f, r2 = 0.0f, r3 = 0.0f, pobj = 0.0f;
    if (valid) {
        r0   = __ldg(myrow + 0);
        r1   = __ldg(myrow + 1);
        r2   = __ldg(myrow + 2);
        r3   = __ldg(myrow + 3);
        pobj = __ldg(myrow + 4);
    }

    // ---- phase 1: per-thread anchor center + argmin over 50 GTs ----
    float ax = 0.0f, ay = 0.0f;
    if (valid) {
        int i, n, s;
        if (a < 6400)      { i = a;        n = 80; s = 8;  }
        else if (a < 8000) { i = a - 6400; n = 40; s = 16; }
        else               { i = a - 8000; n = 20; s = 32; }
        ax = (float)(i % n) * (float)s + (float)s * 0.5f;
        ay = (float)(i / n) * (float)s + (float)s * 0.5f;
    }

    float b0 = INFINITY, b1 = INFINITY;
    int   i0 = 0,        i1 = 1;
    #pragma unroll 5
    for (int m = 0; m < NUM_M; m += 2) {
        float2 c0 = s_ctr[m];
        float2 c1 = s_ctr[m + 1];
        float dx0 = c0.x - ax, dy0 = c0.y - ay;
        float dx1 = c1.x - ax, dy1 = c1.y - ay;
        float d20 = fmaf(dx0, dx0, dy0 * dy0);
        float d21 = fmaf(dx1, dx1, dy1 * dy1);
        if (d20 < b0) { b0 = d20; i0 = m; }
        if (d21 < b1) { b1 = d21; i1 = m + 1; }
    }
    float best = b0; int bidx = i0;
    if (b1 < b0 || (b1 == b0 && i1 < i0)) { best = b1; bidx = i1; }

    const bool  pos  = valid && (best < 4096.0f);   // DIST_THRESH_SQ
    const float posf = pos ? 1.0f : 0.0f;

    float w_obj = 0.0f;
    if (valid) w_obj = sp(pobj) - posf * pobj;      // bce(pobj, posf)

    // ---- phase 2a: warp-cooperative sum of softplus over positive rows ----
    const int wbase = blockIdx.x * BLK + warp * 32;
    float w_cls = 0.0f;

    unsigned pm = __ballot_sync(FULLMASK, pos);     // identical in all lanes
    while (pm) {
        int p0 = __ffs(pm) - 1;
        unsigned pm1 = pm & (pm - 1);
        bool  has1 = (pm1 != 0);
        int   p1   = has1 ? (__ffs(pm1) - 1) : p0;
        float w1   = has1 ? 1.0f : 0.0f;
        pm = has1 ? (pm1 & (pm1 - 1)) : 0u;

        const float* ra = base + (size_t)(wbase + p0) * 85;
        const float* rb = base + (size_t)(wbase + p1) * 85;
        float a0 = __ldg(ra + 5  + lane);
        float a1 = __ldg(ra + 37 + lane);
        float a2 = (lane < 16) ? __ldg(ra + 69 + lane) : -60.0f;
        float q0 = __ldg(rb + 5  + lane);
        float q1 = __ldg(rb + 37 + lane);
        float q2 = (lane < 16) ? __ldg(rb + 69 + lane) : -60.0f;

        float sa = sp(a0) + sp(a1) + sp(a2);
        float sb = sp(q0) + sp(q1) + sp(q2);
        w_cls += sa + w1 * sb;
    }

    // ---- phase 2b + 3: matched-logit subtract + IoU (per-thread, reg-only) ----
    float w_box = 0.0f, w_pos = 0.0f;
    if (pos) {
        int mcls = s_cls[bidx];
        w_cls -= __ldg(myrow + 5 + mcls);           // L1/L2 hit (warp just read row)

        float ew = __expf(r2), eh = __expf(r3);
        float p1x = r0 - ew * 0.5f, p2x = r0 + ew * 0.5f;
        float p1y = r1 - eh * 0.5f, p2y = r1 + eh * 0.5f;
        float ix = fminf(p2x, s_x2[bidx]) - fmaxf(p1x, s_x1[bidx]);
        float iy = fminf(p2y, s_y2[bidx]) - fmaxf(p1y, s_y1[bidx]);
        float inter = fmaxf(ix, 0.0f) * fmaxf(iy, 0.0f);
        float pa    = (p2x - p1x) * (p2y - p1y);
        float uni   = pa + s_ta[bidx] - inter;
        w_box = 1.0f - inter / (uni + 1e-6f);
        w_pos = 1.0f;
    }

    // ---- reduction: warp -> block -> g_part ----
    #pragma unroll
    for (int off = 16; off; off >>= 1) {
        w_obj += __shfl_down_sync(FULLMASK, w_obj, off);
        w_cls += __shfl_down_sync(FULLMASK, w_cls, off);
        w_box += __shfl_down_sync(FULLMASK, w_box, off);
        w_pos += __shfl_down_sync(FULLMASK, w_pos, off);
    }
    if (lane == 0) {
        s_red[warp][0] = w_obj;
        s_red[warp][1] = w_cls;
        s_red[warp][2] = w_box;
        s_red[warp][3] = w_pos;
    }
    __syncthreads();

    if (tid == 0) {
        float o = 0.0f, c = 0.0f, b = 0.0f, p = 0.0f;
        #pragma unroll
        for (int i = 0; i < WARPS; i++) {
            o += s_red[i][0]; c += s_red[i][1];
            b += s_red[i][2]; p += s_red[i][3];
        }
        float* dst = g_part + ((size_t)img * BLKS_IMG + blockIdx.x) * 4;
        dst[0] = o; dst[1] = c; dst[2] = b; dst[3] = p;
        __threadfence();
        unsigned t = atomicAdd(&g_ticket, 1u);
        s_last = (t == NBLOCKS - 1) ? 1 : 0;
    }
    __syncthreads();

    // ---- last block: final reduction (deterministic values) ----
    if (s_last) {
        __shared__ float sw[8][4];
        __shared__ float sfin[4];
        const int rimg = tid >> 2;         // 0..63
        const int comp = tid & 3;          // 0=obj,1=cls,2=box,3=np

        float s = 0.0f;
        const float* p = g_part + (size_t)rimg * BLKS_IMG * 4 + comp;
        #pragma unroll
        for (int b = 0; b < BLKS_IMG; b++) s += p[b * 4];

        float np  = __shfl_sync(FULLMASK, s, lane | 3);
        float den = fmaxf(np, 1.0f);

        float v;
        if (comp == 0)      v = s / 8400.0f;
        else if (comp == 1) v = (np > 0.0f) ? s / (den * 80.0f) : 0.0f;
        else if (comp == 2) v = (np > 0.0f) ? s / den : 0.0f;
        else                v = s;

        #pragma unroll
        for (int off = 4; off < 32; off <<= 1)
            v += __shfl_down_sync(FULLMASK, v, off);

        if (lane < 4) sw[warp][lane] = v;
        __syncthreads();

        if (tid < 4) {
            float t = 0.0f;
            #pragma unroll
            for (int w = 0; w < 8; w++) t += sw[w][tid];
            sfin[tid] = t;
        }
        __syncthreads();

        if (tid == 0) {
            float obj = sfin[0], cls = sfin[1], box = sfin[2], np = sfin[3];
            out[0] = 5.0f * box + obj + cls;
            out[1] = box;
            out[2] = obj;
            out[3] = cls;
            out[4] = np;
            g_ticket = 0;      // reset for next graph replay
        }
    }
}

extern "C" void kernel_launch(void* const* d_in, const int* in_sizes, int n_in,
                              void* d_out, int out_size) {
    const float* pred = (const float*)d_in[0];
    const float* tgt  = (const float*)d_in[1];
    float* out = (float*)d_out;

    dim3 grid(BLKS_IMG, 64);
    yolox_main_kernel<<<grid, BLK>>>(pred, tgt, out);
}